// round 1
// baseline (speedup 1.0000x reference)
#include <cuda_runtime.h>
#include <math.h>

#define B 65536
#define N 512
#define EPSF 1e-8f

// ---------------- scratch (device globals; no allocation allowed) ----------
__device__ __align__(16) float g_sim[B];        // 256 KB
__device__ float g_colpart[512 * N];            // 1 MB: per-pass1-block column sums
__device__ float g_colsum[N];                   // 2 KB
__device__ float g_thirdpart[512];              // 2 KB

__device__ __forceinline__ float warp_max(float v) {
#pragma unroll
    for (int o = 16; o; o >>= 1) v = fmaxf(v, __shfl_xor_sync(0xffffffffu, v, o));
    return v;
}

// ---------------------------------------------------------------------------
// Pass 1: per-row softmax of anchors & neighbors, sim[row] = dot(a_prob, p_prob),
// and per-block column partial sums of a_prob (for entropy of the column mean).
// grid = 512 blocks x 256 threads; 1 warp per row, 16 rows per warp.
// ---------------------------------------------------------------------------
__global__ void __launch_bounds__(256) pass1_kernel(const float* __restrict__ A,
                                                    const float* __restrict__ Nb) {
    const int warp = threadIdx.x >> 5;
    const int lane = threadIdx.x & 31;
    __shared__ float scol[8][N];                 // 16 KB, per-warp column accumulators

    for (int i = threadIdx.x; i < 8 * N; i += 256) (&scol[0][0])[i] = 0.f;
    __syncthreads();

    const int base = (blockIdx.x * 8 + warp) * 16;

    for (int r = 0; r < 16; r++) {
        const int row = base + r;
        const float4* a4 = reinterpret_cast<const float4*>(A  + (size_t)row * N) + lane;
        const float4* n4 = reinterpret_cast<const float4*>(Nb + (size_t)row * N) + lane;

        float a[16], bb[16];
#pragma unroll
        for (int c = 0; c < 4; c++) {
            float4 t = a4[c * 32];
            a[4*c+0] = t.x; a[4*c+1] = t.y; a[4*c+2] = t.z; a[4*c+3] = t.w;
            float4 u = n4[c * 32];
            bb[4*c+0] = u.x; bb[4*c+1] = u.y; bb[4*c+2] = u.z; bb[4*c+3] = u.w;
        }

        float ma = -1e30f, mn = -1e30f;
#pragma unroll
        for (int i = 0; i < 16; i++) { ma = fmaxf(ma, a[i]); mn = fmaxf(mn, bb[i]); }
        ma = warp_max(ma);
        mn = warp_max(mn);

        float sa = 0.f, sb = 0.f, sd = 0.f;
#pragma unroll
        for (int i = 0; i < 16; i++) {
            a[i] = expf(a[i] - ma);
            float e = expf(bb[i] - mn);
            sa += a[i]; sb += e; sd += a[i] * e;
        }
#pragma unroll
        for (int o = 16; o; o >>= 1) {
            sa += __shfl_xor_sync(0xffffffffu, sa, o);
            sb += __shfl_xor_sync(0xffffffffu, sb, o);
            sd += __shfl_xor_sync(0xffffffffu, sd, o);
        }

        if (lane == 0) g_sim[row] = sd / (sa * sb);

        const float inv = 1.f / sa;
#pragma unroll
        for (int c = 0; c < 4; c++) {
            float4* p = reinterpret_cast<float4*>(&scol[warp][c * 128 + 4 * lane]);
            float4 cur = *p;
            cur.x += a[4*c+0] * inv;
            cur.y += a[4*c+1] * inv;
            cur.z += a[4*c+2] * inv;
            cur.w += a[4*c+3] * inv;
            *p = cur;
        }
    }
    __syncthreads();

    for (int col = threadIdx.x; col < N; col += 256) {
        float s = 0.f;
#pragma unroll
        for (int w = 0; w < 8; w++) s += scol[w][col];
        g_colpart[blockIdx.x * N + col] = s;
    }
}

// ---------------------------------------------------------------------------
// Pass 2: third-order term. toe[i] = dot(a_prob[i], sim[512*(i%128) .. +511]).
// Also: each block reduces one column of g_colpart -> g_colsum.
// grid = 512 blocks x 256 threads.
// ---------------------------------------------------------------------------
__global__ void __launch_bounds__(256) pass2_kernel(const float* __restrict__ A) {
    const int warp = threadIdx.x >> 5;
    const int lane = threadIdx.x & 31;
    const int base = (blockIdx.x * 8 + warp) * 16;

    float acc = 0.f;
    for (int r = 0; r < 16; r++) {
        const int row = base + r;
        const float4* a4 = reinterpret_cast<const float4*>(A + (size_t)row * N) + lane;
        const float4* s4 = reinterpret_cast<const float4*>(g_sim + ((row & 127) << 9)) + lane;

        float a[16], sv[16];
#pragma unroll
        for (int c = 0; c < 4; c++) {
            float4 t = a4[c * 32];
            a[4*c+0] = t.x; a[4*c+1] = t.y; a[4*c+2] = t.z; a[4*c+3] = t.w;
            float4 u = s4[c * 32];
            sv[4*c+0] = u.x; sv[4*c+1] = u.y; sv[4*c+2] = u.z; sv[4*c+3] = u.w;
        }

        float ma = -1e30f;
#pragma unroll
        for (int i = 0; i < 16; i++) ma = fmaxf(ma, a[i]);
        ma = warp_max(ma);

        float se = 0.f, sd = 0.f;
#pragma unroll
        for (int i = 0; i < 16; i++) {
            float e = expf(a[i] - ma);
            se += e; sd += e * sv[i];
        }
#pragma unroll
        for (int o = 16; o; o >>= 1) {
            se += __shfl_xor_sync(0xffffffffu, se, o);
            sd += __shfl_xor_sync(0xffffffffu, sd, o);
        }
        if (lane == 0) {
            float toe = sd / se;
            acc += fmaxf(toe, EPSF) * fmaxf(logf(toe), EPSF);
        }
    }

    __shared__ float sw[8];
    __shared__ float scol2[256];
    if (lane == 0) sw[warp] = acc;

    // column reduction: this block owns column blockIdx.x of g_colpart
    {
        float s = 0.f;
        for (int b2 = threadIdx.x; b2 < 512; b2 += 256)
            s += g_colpart[(size_t)b2 * N + blockIdx.x];
        scol2[threadIdx.x] = s;
    }
    __syncthreads();

    if (threadIdx.x == 0) {
        float t = 0.f;
#pragma unroll
        for (int w = 0; w < 8; w++) t += sw[w];
        g_thirdpart[blockIdx.x] = t;
    }
    for (int st = 128; st > 0; st >>= 1) {
        if (threadIdx.x < st) scol2[threadIdx.x] += scol2[threadIdx.x + st];
        __syncthreads();
    }
    if (threadIdx.x == 0) g_colsum[blockIdx.x] = scol2[0];
}

// ---------------------------------------------------------------------------
// Pass 3: final scalar reductions -> 5 outputs.
// ---------------------------------------------------------------------------
__device__ __forceinline__ float block_sum_1024(float v, float* sh) {
    const int tid = threadIdx.x;
    sh[tid] = v; __syncthreads();
    for (int st = 512; st > 0; st >>= 1) {
        if (tid < st) sh[tid] += sh[tid + st];
        __syncthreads();
    }
    float r = sh[0]; __syncthreads();
    return r;
}

__global__ void __launch_bounds__(1024) pass3_kernel(float* __restrict__ out) {
    __shared__ float sh[1024];
    const int tid = threadIdx.x;

    // consistency + second-order over sim
    float cl = 0.f, so = 0.f;
    for (int i = tid; i < B; i += 1024) {
        float s = g_sim[i];
        float l = logf(s);
        cl += fmaxf(l, -100.f);
        so += fmaxf(s, EPSF) * fmaxf(l, EPSF);
    }
    float cl_sum = block_sum_1024(cl, sh);
    float so_sum = block_sum_1024(so, sh);

    // entropy of column means
    float ent = 0.f;
    if (tid < N) {
        float p  = g_colsum[tid] * (1.f / (float)B);
        float p_ = fmaxf(p, EPSF);
        ent = p_ * logf(p_);
    }
    float ent_sum = block_sum_1024(ent, sh);

    // third-order partials
    float th = (tid < 512) ? g_thirdpart[tid] : 0.f;
    float th_sum = block_sum_1024(th, sh);

    if (tid == 0) {
        float consistency = -cl_sum * (1.f / (float)B);
        float entropy     = -ent_sum;
        float second      = so_sum;
        float third       = th_sum * (1.f / (float)N);
        float total = consistency
                    - 2.0f * entropy
                    + (0.25f / (float)N) * second
                    - (0.5f / sqrtf((float)N)) * third;
        out[0] = total;
        out[1] = consistency;
        out[2] = entropy;
        out[3] = second;
        out[4] = third;
    }
}

// ---------------------------------------------------------------------------
extern "C" void kernel_launch(void* const* d_in, const int* in_sizes, int n_in,
                              void* d_out, int out_size) {
    const float* A  = (const float*)d_in[0];   // anchors  [65536, 512]
    const float* Nb = (const float*)d_in[1];   // neighbors[65536, 512]
    float* out = (float*)d_out;

    pass1_kernel<<<512, 256>>>(A, Nb);
    pass2_kernel<<<512, 256>>>(A);
    pass3_kernel<<<1, 1024>>>(out);
}